// round 2
// baseline (speedup 1.0000x reference)
#include <cuda_runtime.h>
#include <math_constants.h>

#define H 512
#define W 512
#define NB 64
#define HW (H * W)
#define NZ (2 * NB)
#define CPW 28              // valid output columns per warp
#define NCS 19              // ceil(512 / 28) column strips
#define RPW 64              // rows per warp
#define WPB 8               // warps per block (8 * 64 = 512 rows)

// Ping-pong skeleton buffers (134 MB each)
__device__ float g_A[(size_t)NZ * HW];
__device__ float g_B[(size_t)NZ * HW];
// Accumulators:
// [0..63]    sum(cl_pred * target) per b     [64..127]  sum(cl_pred) per b
// [128..191] sum(t_skel * pred) per b        [192..255] sum(t_skel) per b
// [256..319] sum(p*t) per b                  [320..383] sum(p) per b
// [384..447] sum(t) per b
__device__ float g_acc[448];

__device__ __forceinline__ float hmin3(float v) {
    float l = __shfl_up_sync(0xffffffffu, v, 1);
    float r = __shfl_down_sync(0xffffffffu, v, 1);
    return fminf(l, fminf(v, r));
}
__device__ __forceinline__ float hmax3(float v) {
    float l = __shfl_up_sync(0xffffffffu, v, 1);
    float r = __shfl_down_sync(0xffffffffu, v, 1);
    return fmaxf(l, fmaxf(v, r));
}

// ---------------------------------------------------------------------------
// One soft-skeletonize iteration: warp-register rolling 5x5 stencil.
//   min_pool = 3x3 min(x)  (x padded +inf); contour = relu(3x3max(mp) - mp)
//   (mp padded -inf outside image); x' = relu(x - contour).
// Each warp: 32 cols loaded (28 valid outputs), RPW rows swept vertically.
// ---------------------------------------------------------------------------
__global__ void __launch_bounds__(256)
skel_step(const float* __restrict__ p0, const float* __restrict__ p1,
          float* __restrict__ dst) {
    const int z = blockIdx.y;
    const float* __restrict__ xp = (z < NB) ? p0 + (size_t)z * HW
                                            : p1 + (size_t)(z - NB) * HW;
    float* __restrict__ op = dst + (size_t)z * HW;

    const int lane = threadIdx.x & 31;
    const int warp = threadIdx.x >> 5;
    const int gc = blockIdx.x * CPW - 2 + lane;
    const bool colin = (gc >= 0) & (gc < W);
    const bool wlane = (lane >= 2) & (lane < 30) & (gc < W);
    const int r0 = warp * RPW;

    const float INF = CUDART_INF_F;
    auto ldx = [&](int r) -> float {
        return (colin && (unsigned)r < (unsigned)H) ? __ldg(xp + r * W + gc) : INF;
    };

    // Warm-up: rows r0-2 .. r0+1
    float x_m2 = ldx(r0 - 2), x_m1 = ldx(r0 - 1);
    float xq0  = ldx(r0),     xq1  = ldx(r0 + 1);
    float hm_m2 = hmin3(x_m2), hm_m1 = hmin3(x_m1);
    float hm_0  = hmin3(xq0),  hm_p1 = hmin3(xq1);

    float mp_m1 = fminf(hm_m2, fminf(hm_m1, hm_0));
    mp_m1 = (colin && (r0 - 1) >= 0) ? mp_m1 : -INF;
    float mp_0 = fminf(hm_m1, fminf(hm_0, hm_p1));
    mp_0 = colin ? mp_0 : -INF;

    float hx_m1 = hmax3(mp_m1);
    float hx_0  = hmax3(mp_0);

    int off = r0 * W + gc;
    #pragma unroll 4
    for (int r = r0; r < r0 + RPW; ++r) {
        float xq2 = ldx(r + 2);
        float hm_p2 = hmin3(xq2);
        float mp_p1 = fminf(hm_0, fminf(hm_p1, hm_p2));
        mp_p1 = (colin && (r + 1) < H) ? mp_p1 : -INF;
        float hx_p1 = hmax3(mp_p1);
        float mxp = fmaxf(hx_m1, fmaxf(hx_0, hx_p1));
        float contour = fmaxf(mxp - mp_0, 0.0f);
        float out = fmaxf(xq0 - contour, 0.0f);
        if (wlane) op[off] = out;
        hx_m1 = hx_0; hx_0 = hx_p1;
        mp_0 = mp_p1;
        hm_0 = hm_p1; hm_p1 = hm_p2;
        xq0 = xq1; xq1 = xq2;
        off += W;
    }
}

// ---------------------------------------------------------------------------
// Final iteration fused with all reductions (no skeleton write-back).
// ---------------------------------------------------------------------------
__global__ void __launch_bounds__(256)
skel_last(const float* __restrict__ p0, const float* __restrict__ p1,
          const float* __restrict__ pred, const float* __restrict__ target) {
    const int z = blockIdx.y;
    const float* __restrict__ xp = (z < NB) ? p0 + (size_t)z * HW
                                            : p1 + (size_t)(z - NB) * HW;
    const int b = (z < NB) ? z : z - NB;
    const float* __restrict__ pb = pred + (size_t)b * HW;
    const float* __restrict__ tb = target + (size_t)b * HW;

    const int lane = threadIdx.x & 31;
    const int warp = threadIdx.x >> 5;
    const int gc = blockIdx.x * CPW - 2 + lane;
    const bool colin = (gc >= 0) & (gc < W);
    const bool wlane = (lane >= 2) & (lane < 30) & (gc < W);
    const int r0 = warp * RPW;

    const float INF = CUDART_INF_F;
    auto ldx = [&](int r) -> float {
        return (colin && (unsigned)r < (unsigned)H) ? __ldg(xp + r * W + gc) : INF;
    };

    float x_m2 = ldx(r0 - 2), x_m1 = ldx(r0 - 1);
    float xq0  = ldx(r0),     xq1  = ldx(r0 + 1);
    float hm_m2 = hmin3(x_m2), hm_m1 = hmin3(x_m1);
    float hm_0  = hmin3(xq0),  hm_p1 = hmin3(xq1);

    float mp_m1 = fminf(hm_m2, fminf(hm_m1, hm_0));
    mp_m1 = (colin && (r0 - 1) >= 0) ? mp_m1 : -INF;
    float mp_0 = fminf(hm_m1, fminf(hm_0, hm_p1));
    mp_0 = colin ? mp_0 : -INF;

    float hx_m1 = hmax3(mp_m1);
    float hx_0  = hmax3(mp_0);

    float s0 = 0, s1 = 0, s2 = 0, s3 = 0, s4 = 0;

    int off = r0 * W + gc;
    #pragma unroll 4
    for (int r = r0; r < r0 + RPW; ++r) {
        float xq2 = ldx(r + 2);
        float hm_p2 = hmin3(xq2);
        float mp_p1 = fminf(hm_0, fminf(hm_p1, hm_p2));
        mp_p1 = (colin && (r + 1) < H) ? mp_p1 : -INF;
        float hx_p1 = hmax3(mp_p1);
        float mxp = fmaxf(hx_m1, fmaxf(hx_0, hx_p1));
        float contour = fmaxf(mxp - mp_0, 0.0f);
        float out = fmaxf(xq0 - contour, 0.0f);
        if (wlane) {
            if (z < NB) {  // out = cl_pred pixel; also dice terms
                float tv = __ldg(tb + off);
                float pv = __ldg(pb + off);
                s0 += out * tv;   // cl_pred * target
                s1 += out;        // cl_pred
                s2 += pv * tv;    // p*t
                s3 += pv;         // p
                s4 += tv;         // t
            } else {       // out = target_skeleton pixel
                float pv = __ldg(pb + off);
                s0 += out * pv;   // t_skel * pred
                s1 += out;        // t_skel
            }
        }
        hx_m1 = hx_0; hx_0 = hx_p1;
        mp_0 = mp_p1;
        hm_0 = hm_p1; hm_p1 = hm_p2;
        xq0 = xq1; xq1 = xq2;
        off += W;
    }

    // warp reduce
    #pragma unroll
    for (int o = 16; o; o >>= 1) {
        s0 += __shfl_down_sync(0xffffffffu, s0, o);
        s1 += __shfl_down_sync(0xffffffffu, s1, o);
        s2 += __shfl_down_sync(0xffffffffu, s2, o);
        s3 += __shfl_down_sync(0xffffffffu, s3, o);
        s4 += __shfl_down_sync(0xffffffffu, s4, o);
    }
    __shared__ float sred[WPB][5];
    if (lane == 0) {
        sred[warp][0] = s0; sred[warp][1] = s1; sred[warp][2] = s2;
        sred[warp][3] = s3; sred[warp][4] = s4;
    }
    __syncthreads();
    if (threadIdx.x < 5) {
        float v = 0;
        #pragma unroll
        for (int w = 0; w < WPB; w++) v += sred[w][threadIdx.x];
        int q = threadIdx.x;
        if (z < NB) {
            // q: 0->clp*t, 1->clp, 2->p*t, 3->p, 4->t
            int base = (q == 0) ? 0 : (q == 1) ? 64 : (q == 2) ? 256 : (q == 3) ? 320 : 384;
            atomicAdd(&g_acc[base + b], v);
        } else if (q < 2) {
            atomicAdd(&g_acc[(q == 0 ? 128 : 192) + b], v);
        }
    }
}

// ---------------------------------------------------------------------------
__global__ void zero_acc() {
    int i = blockIdx.x * blockDim.x + threadIdx.x;
    if (i < 448) g_acc[i] = 0.0f;
}

__global__ void finalize_kernel(float* __restrict__ out) {
    int b = threadIdx.x;  // 64 threads
    float ifl = (g_acc[b] + 1.0f) / (g_acc[64 + b] + 1.0f);
    float tfl = (g_acc[128 + b] + 1.0f) / (g_acc[192 + b] + 1.0f);
    float it = ifl * tfl;
    float s  = ifl + tfl;
    float pt = g_acc[256 + b];
    float sp = g_acc[320 + b];
    float st = g_acc[384 + b];
    #pragma unroll
    for (int o = 16; o; o >>= 1) {
        it += __shfl_down_sync(0xffffffffu, it, o);
        s  += __shfl_down_sync(0xffffffffu, s,  o);
        pt += __shfl_down_sync(0xffffffffu, pt, o);
        sp += __shfl_down_sync(0xffffffffu, sp, o);
        st += __shfl_down_sync(0xffffffffu, st, o);
    }
    __shared__ float sh[5][2];
    if ((threadIdx.x & 31) == 0) {
        int w = threadIdx.x >> 5;
        sh[0][w] = it; sh[1][w] = s; sh[2][w] = pt; sh[3][w] = sp; sh[4][w] = st;
    }
    __syncthreads();
    if (threadIdx.x == 0) {
        float IT = sh[0][0] + sh[0][1];
        float S  = sh[1][0] + sh[1][1];
        float I  = sh[2][0] + sh[2][1];
        float Sp = sh[3][0] + sh[3][1];
        float St = sh[4][0] + sh[4][1];
        float dice   = 1.0f - (2.0f * I + 1e-6f) / (Sp + St + 1e-6f);
        float cldice = 1.0f - 2.0f * IT / S;
        out[0] = 0.8f * dice + 0.2f * cldice;
    }
}

// ---------------------------------------------------------------------------
extern "C" void kernel_launch(void* const* d_in, const int* in_sizes, int n_in,
                              void* d_out, int out_size) {
    const float* pred   = (const float*)d_in[0];
    const float* target = (const float*)d_in[1];
    float* out = (float*)d_out;

    zero_acc<<<1, 448>>>();

    dim3 blk(256);
    dim3 grd(NCS, NZ);  // 19 x 128

    // iter 1: inputs -> A
    skel_step<<<grd, blk>>>(pred, target, g_A);
    // iters 2..9: ping-pong. even iters A->B, odd iters B->A. After iter 9 -> A.
    for (int k = 2; k <= 9; k++) {
        if (k & 1) skel_step<<<grd, blk>>>(g_B, g_B + (size_t)NB * HW, g_A);
        else       skel_step<<<grd, blk>>>(g_A, g_A + (size_t)NB * HW, g_B);
    }
    // iter 10 fused with reductions (reads A)
    skel_last<<<grd, blk>>>(g_A, g_A + (size_t)NB * HW, pred, target);

    finalize_kernel<<<1, 64>>>(out);
}

// round 3
// speedup vs baseline: 21.3327x; 21.3327x over previous
#include <cuda_runtime.h>
#include <math_constants.h>

#define H 512
#define W 512
#define NB 64
#define HW (H * W)
#define NZ (2 * NB)
#define CPW 28              // valid output columns per warp
#define NCS 19              // ceil(512 / 28) column strips
#define RPW 64              // rows per warp
#define WPB 8               // warps per block (8 * 64 = 512 rows)

// Ping-pong skeleton buffers (134 MB each). Referenced ONLY from device code.
__device__ float g_A[(size_t)NZ * HW];
__device__ float g_B[(size_t)NZ * HW];
// Accumulators:
// [0..63]    sum(cl_pred * target) per b     [64..127]  sum(cl_pred) per b
// [128..191] sum(t_skel * pred) per b        [192..255] sum(t_skel) per b
// [256..319] sum(p*t) per b                  [320..383] sum(p) per b
// [384..447] sum(t) per b
__device__ float g_acc[448];

__device__ __forceinline__ float hmin3(float v) {
    float l = __shfl_up_sync(0xffffffffu, v, 1);
    float r = __shfl_down_sync(0xffffffffu, v, 1);
    return fminf(l, fminf(v, r));
}
__device__ __forceinline__ float hmax3(float v) {
    float l = __shfl_up_sync(0xffffffffu, v, 1);
    float r = __shfl_down_sync(0xffffffffu, v, 1);
    return fmaxf(l, fmaxf(v, r));
}

// ---------------------------------------------------------------------------
// One soft-skeletonize iteration: warp-register rolling 5x5 stencil.
//   min_pool = 3x3 min(x)  (x padded +inf); contour = relu(3x3max(mp) - mp)
//   (mp padded -inf outside image); x' = relu(x - contour).
// mode 0: inputs (pred/target args) -> g_A
// mode 1: g_A -> g_B
// mode 2: g_B -> g_A
// ---------------------------------------------------------------------------
__global__ void __launch_bounds__(256)
skel_step(int mode, const float* __restrict__ pred,
          const float* __restrict__ target) {
    const int z = blockIdx.y;
    const float* __restrict__ xp;
    float* __restrict__ op;
    if (mode == 0) {
        xp = (z < NB) ? pred + (size_t)z * HW : target + (size_t)(z - NB) * HW;
        op = g_A + (size_t)z * HW;
    } else if (mode == 1) {
        xp = g_A + (size_t)z * HW;
        op = g_B + (size_t)z * HW;
    } else {
        xp = g_B + (size_t)z * HW;
        op = g_A + (size_t)z * HW;
    }

    const int lane = threadIdx.x & 31;
    const int warp = threadIdx.x >> 5;
    const int gc = blockIdx.x * CPW - 2 + lane;
    const bool colin = (gc >= 0) & (gc < W);
    const bool wlane = (lane >= 2) & (lane < 30) & (gc < W);
    const int r0 = warp * RPW;

    const float INF = CUDART_INF_F;
    auto ldx = [&](int r) -> float {
        return (colin && (unsigned)r < (unsigned)H) ? __ldg(xp + r * W + gc) : INF;
    };

    // Warm-up: rows r0-2 .. r0+1
    float x_m2 = ldx(r0 - 2), x_m1 = ldx(r0 - 1);
    float xq0  = ldx(r0),     xq1  = ldx(r0 + 1);
    float hm_m2 = hmin3(x_m2), hm_m1 = hmin3(x_m1);
    float hm_0  = hmin3(xq0),  hm_p1 = hmin3(xq1);

    float mp_m1 = fminf(hm_m2, fminf(hm_m1, hm_0));
    mp_m1 = (colin && (r0 - 1) >= 0) ? mp_m1 : -INF;
    float mp_0 = fminf(hm_m1, fminf(hm_0, hm_p1));
    mp_0 = colin ? mp_0 : -INF;

    float hx_m1 = hmax3(mp_m1);
    float hx_0  = hmax3(mp_0);

    int off = r0 * W + gc;
    #pragma unroll 4
    for (int r = r0; r < r0 + RPW; ++r) {
        float xq2 = ldx(r + 2);
        float hm_p2 = hmin3(xq2);
        float mp_p1 = fminf(hm_0, fminf(hm_p1, hm_p2));
        mp_p1 = (colin && (r + 1) < H) ? mp_p1 : -INF;
        float hx_p1 = hmax3(mp_p1);
        float mxp = fmaxf(hx_m1, fmaxf(hx_0, hx_p1));
        float contour = fmaxf(mxp - mp_0, 0.0f);
        float out = fmaxf(xq0 - contour, 0.0f);
        if (wlane) op[off] = out;
        hx_m1 = hx_0; hx_0 = hx_p1;
        mp_0 = mp_p1;
        hm_0 = hm_p1; hm_p1 = hm_p2;
        xq0 = xq1; xq1 = xq2;
        off += W;
    }
}

// ---------------------------------------------------------------------------
// Final iteration fused with all reductions (reads g_A; no skeleton write).
// ---------------------------------------------------------------------------
__global__ void __launch_bounds__(256)
skel_last(const float* __restrict__ pred, const float* __restrict__ target) {
    const int z = blockIdx.y;
    const float* __restrict__ xp = g_A + (size_t)z * HW;
    const int b = (z < NB) ? z : z - NB;
    const float* __restrict__ pb = pred + (size_t)b * HW;
    const float* __restrict__ tb = target + (size_t)b * HW;

    const int lane = threadIdx.x & 31;
    const int warp = threadIdx.x >> 5;
    const int gc = blockIdx.x * CPW - 2 + lane;
    const bool colin = (gc >= 0) & (gc < W);
    const bool wlane = (lane >= 2) & (lane < 30) & (gc < W);
    const int r0 = warp * RPW;

    const float INF = CUDART_INF_F;
    auto ldx = [&](int r) -> float {
        return (colin && (unsigned)r < (unsigned)H) ? __ldg(xp + r * W + gc) : INF;
    };

    float x_m2 = ldx(r0 - 2), x_m1 = ldx(r0 - 1);
    float xq0  = ldx(r0),     xq1  = ldx(r0 + 1);
    float hm_m2 = hmin3(x_m2), hm_m1 = hmin3(x_m1);
    float hm_0  = hmin3(xq0),  hm_p1 = hmin3(xq1);

    float mp_m1 = fminf(hm_m2, fminf(hm_m1, hm_0));
    mp_m1 = (colin && (r0 - 1) >= 0) ? mp_m1 : -INF;
    float mp_0 = fminf(hm_m1, fminf(hm_0, hm_p1));
    mp_0 = colin ? mp_0 : -INF;

    float hx_m1 = hmax3(mp_m1);
    float hx_0  = hmax3(mp_0);

    float s0 = 0, s1 = 0, s2 = 0, s3 = 0, s4 = 0;

    int off = r0 * W + gc;
    #pragma unroll 4
    for (int r = r0; r < r0 + RPW; ++r) {
        float xq2 = ldx(r + 2);
        float hm_p2 = hmin3(xq2);
        float mp_p1 = fminf(hm_0, fminf(hm_p1, hm_p2));
        mp_p1 = (colin && (r + 1) < H) ? mp_p1 : -INF;
        float hx_p1 = hmax3(mp_p1);
        float mxp = fmaxf(hx_m1, fmaxf(hx_0, hx_p1));
        float contour = fmaxf(mxp - mp_0, 0.0f);
        float out = fmaxf(xq0 - contour, 0.0f);
        if (wlane) {
            if (z < NB) {  // out = cl_pred pixel; also dice terms
                float tv = __ldg(tb + off);
                float pv = __ldg(pb + off);
                s0 += out * tv;   // cl_pred * target
                s1 += out;        // cl_pred
                s2 += pv * tv;    // p*t
                s3 += pv;         // p
                s4 += tv;         // t
            } else {       // out = target_skeleton pixel
                float pv = __ldg(pb + off);
                s0 += out * pv;   // t_skel * pred
                s1 += out;        // t_skel
            }
        }
        hx_m1 = hx_0; hx_0 = hx_p1;
        mp_0 = mp_p1;
        hm_0 = hm_p1; hm_p1 = hm_p2;
        xq0 = xq1; xq1 = xq2;
        off += W;
    }

    // warp reduce
    #pragma unroll
    for (int o = 16; o; o >>= 1) {
        s0 += __shfl_down_sync(0xffffffffu, s0, o);
        s1 += __shfl_down_sync(0xffffffffu, s1, o);
        s2 += __shfl_down_sync(0xffffffffu, s2, o);
        s3 += __shfl_down_sync(0xffffffffu, s3, o);
        s4 += __shfl_down_sync(0xffffffffu, s4, o);
    }
    __shared__ float sred[WPB][5];
    if (lane == 0) {
        sred[warp][0] = s0; sred[warp][1] = s1; sred[warp][2] = s2;
        sred[warp][3] = s3; sred[warp][4] = s4;
    }
    __syncthreads();
    if (threadIdx.x < 5) {
        float v = 0;
        #pragma unroll
        for (int w = 0; w < WPB; w++) v += sred[w][threadIdx.x];
        int q = threadIdx.x;
        if (z < NB) {
            int base = (q == 0) ? 0 : (q == 1) ? 64 : (q == 2) ? 256 : (q == 3) ? 320 : 384;
            atomicAdd(&g_acc[base + b], v);
        } else if (q < 2) {
            atomicAdd(&g_acc[(q == 0 ? 128 : 192) + b], v);
        }
    }
}

// ---------------------------------------------------------------------------
__global__ void zero_acc() {
    int i = threadIdx.x;
    if (i < 448) g_acc[i] = 0.0f;
}

__global__ void finalize_kernel(float* __restrict__ out) {
    int b = threadIdx.x;  // 64 threads
    float ifl = (g_acc[b] + 1.0f) / (g_acc[64 + b] + 1.0f);
    float tfl = (g_acc[128 + b] + 1.0f) / (g_acc[192 + b] + 1.0f);
    float it = ifl * tfl;
    float s  = ifl + tfl;
    float pt = g_acc[256 + b];
    float sp = g_acc[320 + b];
    float st = g_acc[384 + b];
    #pragma unroll
    for (int o = 16; o; o >>= 1) {
        it += __shfl_down_sync(0xffffffffu, it, o);
        s  += __shfl_down_sync(0xffffffffu, s,  o);
        pt += __shfl_down_sync(0xffffffffu, pt, o);
        sp += __shfl_down_sync(0xffffffffu, sp, o);
        st += __shfl_down_sync(0xffffffffu, st, o);
    }
    __shared__ float sh[5][2];
    if ((threadIdx.x & 31) == 0) {
        int w = threadIdx.x >> 5;
        sh[0][w] = it; sh[1][w] = s; sh[2][w] = pt; sh[3][w] = sp; sh[4][w] = st;
    }
    __syncthreads();
    if (threadIdx.x == 0) {
        float IT = sh[0][0] + sh[0][1];
        float S  = sh[1][0] + sh[1][1];
        float I  = sh[2][0] + sh[2][1];
        float Sp = sh[3][0] + sh[3][1];
        float St = sh[4][0] + sh[4][1];
        float dice   = 1.0f - (2.0f * I + 1e-6f) / (Sp + St + 1e-6f);
        float cldice = 1.0f - 2.0f * IT / S;
        out[0] = 0.8f * dice + 0.2f * cldice;
    }
}

// ---------------------------------------------------------------------------
extern "C" void kernel_launch(void* const* d_in, const int* in_sizes, int n_in,
                              void* d_out, int out_size) {
    const float* pred   = (const float*)d_in[0];
    const float* target = (const float*)d_in[1];
    float* out = (float*)d_out;

    zero_acc<<<1, 448>>>();

    dim3 blk(256);
    dim3 grd(NCS, NZ);  // 19 x 128

    // iter 1: inputs -> A
    skel_step<<<grd, blk>>>(0, pred, target);
    // iters 2..9: ping-pong. even iters A->B (mode 1), odd iters B->A (mode 2).
    // After iter 9 the state is in A.
    for (int k = 2; k <= 9; k++) {
        skel_step<<<grd, blk>>>((k & 1) ? 2 : 1, pred, target);
    }
    // iter 10 fused with reductions (reads A)
    skel_last<<<grd, blk>>>(pred, target);

    finalize_kernel<<<1, 64>>>(out);
}